// round 14
// baseline (speedup 1.0000x reference)
#include <cuda_runtime.h>
#include <cuda_fp16.h>
#include <math.h>
#include <stdint.h>

#define NTOK 8192
#define DIM  1024
#define NEXP 8
#define HID  1024
#define PMAX64 8320          // padded M (multiple of 64)
#define CAPACITY 1280.0f

#define KC     64            // K elements per pipeline stage (fp16: 128B rows)
#define NCHUNK 16            // 1024 / 64
#define NSTAGE 3
#define A_B    (64 * 128)          // 8192 B: 64x64 fp16 A tile
#define B_B    (128 * 128)         // 16384 B: 128x64 fp16 B tile
#define STAGE_B (A_B + B_B)        // 24576
#define HDR    2048                // 192 src ptrs (1536B) + 64 pred ints
#define SMEM_GEMM (HDR + NSTAGE * STAGE_B)   // 75776 -> 3 CTAs/SM

// ---------------- scratch globals ----------------
__device__ int   g_topi[NTOK * 2];
__device__ float g_topw[NTOK * 2];
__device__ int   g_nent[NTOK];
__device__ int   g_cnt[NEXP];
__device__ int   g_ptok[NEXP * PMAX64];
__device__ int   g_pslot[NEXP * PMAX64];
__device__ float g_pw[NEXP * PMAX64];
__device__ __align__(256) __half g_xh[(size_t)NTOK * DIM];
__device__ __align__(256) __half g_w1[(size_t)NEXP * HID * DIM];   // [e][n][k] fp16
__device__ __align__(256) __half g_w2[(size_t)NEXP * DIM * HID];   // [e][n][k] fp16
__device__ __align__(256) __half g_y1h[(size_t)NEXP * PMAX64 * HID];
__device__ float g_pout[(size_t)NTOK * 4 * DIM];

// ---------------- small helpers ----------------
__device__ __forceinline__ uint32_t packh2(__half a, __half b) {
    __half2 t = __halves2half2(a, b);
    return *reinterpret_cast<uint32_t*>(&t);
}
__device__ __forceinline__ float gelu_f(float v) {
    return 0.5f * v * (1.0f + erff(v * 0.70710678118654752f));
}
__device__ __forceinline__ uint32_t smem_u32(const void* p) {
    uint32_t a;
    asm("{ .reg .u64 t; cvta.to.shared.u64 t, %1; cvt.u32.u64 %0, t; }" : "=r"(a) : "l"(p));
    return a;
}

#define LDSM_X4(r, addr) \
    asm volatile("ldmatrix.sync.aligned.m8n8.x4.shared.b16 {%0,%1,%2,%3}, [%4];" \
        : "=r"((r)[0]), "=r"((r)[1]), "=r"((r)[2]), "=r"((r)[3]) : "r"(addr))
#define MMA16816H(c, a, b) \
    asm volatile("mma.sync.aligned.m16n8k16.row.col.f32.f16.f16.f32 " \
        "{%0,%1,%2,%3}, {%4,%5,%6,%7}, {%8,%9}, {%0,%1,%2,%3};" \
        : "+f"((c)[0]), "+f"((c)[1]), "+f"((c)[2]), "+f"((c)[3]) \
        : "r"((a)[0]), "r"((a)[1]), "r"((a)[2]), "r"((a)[3]), "r"((b)[0]), "r"((b)[1]))

// swizzled byte offset within an N-row x 128B tile
__device__ __forceinline__ uint32_t swz(uint32_t row, uint32_t seg) {
    return row * 128u + ((seg ^ (row & 7u)) * 16u);
}

// ---------------- fused router + x->fp16 ----------------
__global__ __launch_bounds__(256) void router_split_kernel(
        const float* __restrict__ x,
        const float* __restrict__ rw,
        const float* __restrict__ rb) {
    __shared__ float s_rw[DIM * 9];          // [k*9 + e]
    const int tid = threadIdx.x, lane = tid & 31, wid = tid >> 5;
    for (int i = tid; i < DIM * NEXP; i += 256) {
        int k = i >> 3, e = i & 7;
        s_rw[k * 9 + e] = rw[i];
    }
    __syncthreads();

    const int n = blockIdx.x * 8 + wid;
    const float* xr = x + (size_t)n * DIM;
    float acc[NEXP];
#pragma unroll
    for (int e = 0; e < NEXP; e++) acc[e] = 0.f;

#pragma unroll 4
    for (int i = 0; i < 16; i++) {
        const int k = i * 64 + lane * 2;
        float2 v = *(const float2*)(xr + k);
        *(uint32_t*)(g_xh + (size_t)n * DIM + k) =
            packh2(__float2half_rn(v.x), __float2half_rn(v.y));
        const float* r0 = s_rw + k * 9;
        const float* r1 = s_rw + (k + 1) * 9;
#pragma unroll
        for (int e = 0; e < NEXP; e++) acc[e] += v.x * r0[e] + v.y * r1[e];
    }
#pragma unroll
    for (int off = 16; off > 0; off >>= 1)
#pragma unroll
        for (int e = 0; e < NEXP; e++)
            acc[e] += __shfl_xor_sync(0xFFFFFFFFu, acc[e], off);

    if (lane == 0) {
        float l[NEXP];
#pragma unroll
        for (int e = 0; e < NEXP; e++) l[e] = acc[e] + rb[e];
        float m = l[0];
#pragma unroll
        for (int e = 1; e < NEXP; e++) m = fmaxf(m, l[e]);
        float p[NEXP], sum = 0.f;
#pragma unroll
        for (int e = 0; e < NEXP; e++) { p[e] = expf(l[e] - m); sum += p[e]; }
#pragma unroll
        for (int e = 0; e < NEXP; e++) p[e] /= sum;
        int i0 = 0;
        for (int e = 1; e < NEXP; e++) if (p[e] > p[i0]) i0 = e;
        int i1 = (i0 == 0) ? 1 : 0;
        for (int e = 0; e < NEXP; e++) if (e != i0 && p[e] > p[i1]) i1 = e;
        float s2 = p[i0] + p[i1];
        g_topi[n * 2 + 0] = i0;  g_topi[n * 2 + 1] = i1;
        g_topw[n * 2 + 0] = p[i0] / s2;  g_topw[n * 2 + 1] = p[i1] / s2;
    }
}

// ---------------- fused corr + dispatch build (ONE block, 1024 threads) ----------------
__global__ __launch_bounds__(1024) void dispatch_kernel() {
    __shared__ float s_wred[32][16];
    __shared__ float s_corr[16];
    __shared__ int   s_cnt[NEXP];
    const int tid = threadIdx.x, lane = tid & 31, wid = tid >> 5;

    float a[16];
#pragma unroll
    for (int q = 0; q < 16; q++) a[q] = 0.f;
    for (int i = tid; i < NTOK; i += 1024) {
        int e0 = g_topi[i * 2 + 0], e1 = g_topi[i * 2 + 1];
        float w0 = g_topw[i * 2 + 0], w1 = g_topw[i * 2 + 1];
#pragma unroll
        for (int e = 0; e < NEXP; e++) {
            a[e * 2 + 0] += (e0 == e) ? w0 : 0.f;
            a[e * 2 + 1] += (e1 == e) ? w1 : 0.f;
        }
    }
#pragma unroll
    for (int off = 16; off > 0; off >>= 1)
#pragma unroll
        for (int q = 0; q < 16; q++)
            a[q] += __shfl_xor_sync(0xFFFFFFFFu, a[q], off);
    if (lane == 0)
#pragma unroll
        for (int q = 0; q < 16; q++) s_wred[wid][q] = a[q];
    if (tid < NEXP) s_cnt[tid] = 0;
    __syncthreads();
    if (tid < 16) {
        float s = 0.f;
        for (int w = 0; w < 32; w++) s += s_wred[w][tid];
        s_corr[tid] = s;
    }
    __syncthreads();

    for (int n = tid; n < NTOK; n += 1024) {
        int ee[4]; float ww[4]; int ne = 2;
        ee[0] = g_topi[n * 2 + 0]; ww[0] = g_topw[n * 2 + 0];
        ee[1] = g_topi[n * 2 + 1]; ww[1] = g_topw[n * 2 + 1];
        if (n < NEXP) {
#pragma unroll
            for (int j = 0; j < 2; j++) {
                float c = s_corr[n * 2 + j];
                int f = -1;
                for (int s = 0; s < ne; s++) if (ee[s] == j) f = s;
                if (f >= 0) ww[f] += c;
                else if (c != 0.0f) { ee[ne] = j; ww[ne] = c; ne++; }
            }
        }
        g_nent[n] = ne;
        for (int s = 0; s < ne; s++) {
            float w = fminf(ww[s], CAPACITY);
            int e = ee[s];
            int idx = atomicAdd(&s_cnt[e], 1);
            g_ptok[e * PMAX64 + idx] = n;
            g_pslot[e * PMAX64 + idx] = s;
            g_pw[e * PMAX64 + idx] = w;
        }
    }
    __syncthreads();
    if (tid < NEXP) g_cnt[tid] = s_cnt[tid];
}

// ---------------- prep: transpose BOTH weights  w[e][k][n] -> [e][n][k] fp16 ----------------
__global__ void tsplit_kernel(const float* __restrict__ w1s, const float* __restrict__ w2s) {
    __shared__ float t[32][33];
    const int z = blockIdx.z;
    const int e = z & 7;
    const float* w = (z < 8) ? w1s : w2s;
    __half* oh = (z < 8) ? g_w1 : g_w2;
    int k0 = blockIdx.y * 32, n0 = blockIdx.x * 32;
    int tx = threadIdx.x, ty = threadIdx.y;
    const float* wp = w + (size_t)e * DIM * HID;
#pragma unroll
    for (int r = 0; r < 32; r += 8)
        t[ty + r][tx] = wp[(size_t)(k0 + ty + r) * HID + n0 + tx];
    __syncthreads();
#pragma unroll
    for (int r = 0; r < 32; r += 8) {
        float v = t[tx][ty + r];
        size_t o = ((size_t)e * HID + n0 + ty + r) * DIM + k0 + tx;
        oh[o] = __float2half_rn(v);
    }
}

// ---------------- GEMM mainloop (64x128 CTA tile) ----------------
__device__ __forceinline__ void load_stage(char* smem, uint32_t sb, int tid, int c) {
    const __half* const* s_ptr = (const __half* const*)smem;     // 192 entries: 64 A + 128 B
    const int* s_pred = (const int*)(smem + 1536);               // 64 entries
    const int kel = c * KC;
    const uint32_t sbase = sb + HDR + (uint32_t)((c % NSTAGE) * STAGE_B);
#pragma unroll
    for (int it = 0; it < 6; it++) {
        const int id = tid + it * 256;                            // 0..1535
        if (id < 512) {                                           // A: 64 rows x 8 segs
            const int row = id >> 3, seg = id & 7;
            const char* src = (const char*)(s_ptr[row] + kel) + seg * 16;
            uint32_t dst = sbase + swz(row, seg);
            int sz = s_pred[row];
            asm volatile("cp.async.cg.shared.global [%0], [%1], 16, %2;"
                         :: "r"(dst), "l"(src), "r"(sz) : "memory");
        } else {                                                  // B: 128 rows x 8 segs
            const int bid2 = id - 512;
            const int row = bid2 >> 3, seg = bid2 & 7;
            const char* src = (const char*)(s_ptr[64 + row] + kel) + seg * 16;
            uint32_t dst = sbase + A_B + swz(row, seg);
            asm volatile("cp.async.cg.shared.global [%0], [%1], 16, 16;"
                         :: "r"(dst), "l"(src) : "memory");
        }
    }
    asm volatile("cp.async.commit_group;" ::: "memory");
}

__device__ __forceinline__ void compute_stage(uint32_t sb, int tid, int buf, float acc[2][4][4]) {
    const int lane = tid & 31, wid = tid >> 5;
    const int wr = wid >> 2, wc = wid & 3;
    const uint32_t base = sb + HDR + (uint32_t)(buf * STAGE_B);
    const uint32_t arow = wr * 32 + (lane & 15);
    const uint32_t asegbit = (lane >> 4) & 1;
    const uint32_t brow = wc * 32 + ((lane >> 4) & 1) * 8 + (lane & 7);
    const uint32_t bsegbit = (lane >> 3) & 1;
#pragma unroll
    for (int kst = 0; kst < 4; kst++) {
        const uint32_t aseg = kst * 2 + asegbit;
        const uint32_t bseg = kst * 2 + bsegbit;
        uint32_t ah[2][4], bb[2][4];
        LDSM_X4(ah[0], base + swz(arow, aseg));
        LDSM_X4(bb[0], base + A_B + swz(brow, bseg));
        LDSM_X4(bb[1], base + A_B + swz(brow + 16, bseg));
        LDSM_X4(ah[1], base + swz(arow + 16, aseg));
#pragma unroll
        for (int mt = 0; mt < 2; mt++)
#pragma unroll
            for (int nt = 0; nt < 4; nt++)
                MMA16816H(acc[mt][nt], ah[mt], &bb[nt >> 1][(nt & 1) * 2]);
    }
}

__device__ __forceinline__ void gemm_mainloop(char* smem, uint32_t sb, int tid, float acc[2][4][4]) {
#pragma unroll
    for (int mt = 0; mt < 2; mt++)
#pragma unroll
        for (int nt = 0; nt < 4; nt++)
#pragma unroll
            for (int i = 0; i < 4; i++) acc[mt][nt][i] = 0.f;
    load_stage(smem, sb, tid, 0);
    load_stage(smem, sb, tid, 1);
#pragma unroll 1
    for (int c = 0; c < NCHUNK; c++) {
        if (c == NCHUNK - 1) asm volatile("cp.async.wait_group 0;" ::: "memory");
        else                 asm volatile("cp.async.wait_group 1;" ::: "memory");
        __syncthreads();   // c's data visible; buffer (c+2)%3 free (compute c-1 done)
        if (c + 2 < NCHUNK) load_stage(smem, sb, tid, c + 2);
        compute_stage(sb, tid, c % NSTAGE, acc);
    }
}

// ---------------- GEMM1: y1 = gelu(w * (x @ W1) + b1) -> fp16 ----------------
__global__ __launch_bounds__(256, 3) void gemm1_tc(const float* __restrict__ b1) {
    const int e = blockIdx.z;
    const int M = g_cnt[e];
    const int m0 = blockIdx.y * 64;
    if (m0 >= M) return;
    const int n0 = blockIdx.x * 128;
    extern __shared__ char smem[];
    const uint32_t sb = smem_u32(smem);
    const int tid = threadIdx.x;

    {
        const __half** s_ptr = (const __half**)smem;
        int* s_pred = (int*)(smem + 1536);
        if (tid < 64) {
            int p = m0 + tid;
            bool v = p < M;
            int tok = v ? g_ptok[e * PMAX64 + p] : 0;
            s_ptr[tid] = g_xh + (size_t)tok * DIM;
            s_pred[tid] = v ? 16 : 0;
        } else if (tid < 192) {
            int r = tid - 64;
            s_ptr[64 + r] = g_w1 + ((size_t)e * HID + n0 + r) * DIM;
        }
    }
    __syncthreads();

    float acc[2][4][4];
    gemm_mainloop(smem, sb, tid, acc);

    const int lane = tid & 31, wid = tid >> 5;
    const int wr = wid >> 2, wc = wid & 3;
    const int gid = lane >> 2, tig = lane & 3;
    const float* b1e = b1 + e * HID + n0 + wc * 32;
#pragma unroll
    for (int mt = 0; mt < 2; mt++) {
        const int p0 = m0 + wr * 32 + mt * 16 + gid;
        const int p1 = p0 + 8;
        const bool v0 = p0 < M, v1 = p1 < M;
        const float w0 = v0 ? g_pw[e * PMAX64 + p0] : 0.f;
        const float w1 = v1 ? g_pw[e * PMAX64 + p1] : 0.f;
        __half* oh0 = g_y1h + ((size_t)(e * PMAX64 + p0)) * HID + n0 + wc * 32;
        __half* oh1 = g_y1h + ((size_t)(e * PMAX64 + p1)) * HID + n0 + wc * 32;
#pragma unroll
        for (int nt = 0; nt < 4; nt++) {
            const int co = nt * 8 + 2 * tig;
            const float* c = acc[mt][nt];
            if (v0) {
                float t0 = gelu_f(w0 * c[0] + b1e[co]);
                float t1 = gelu_f(w0 * c[1] + b1e[co + 1]);
                *(uint32_t*)(oh0 + co) = packh2(__float2half_rn(t0), __float2half_rn(t1));
            }
            if (v1) {
                float t0 = gelu_f(w1 * c[2] + b1e[co]);
                float t1 = gelu_f(w1 * c[3] + b1e[co + 1]);
                *(uint32_t*)(oh1 + co) = packh2(__float2half_rn(t0), __float2half_rn(t1));
            }
        }
    }
}

// ---------------- GEMM2: pout = w * (y1 @ W2 + b2) ----------------
__global__ __launch_bounds__(256, 3) void gemm2_tc(const float* __restrict__ b2) {
    const int e = blockIdx.z;
    const int M = g_cnt[e];
    const int m0 = blockIdx.y * 64;
    if (m0 >= M) return;
    const int n0 = blockIdx.x * 128;
    extern __shared__ char smem[];
    const uint32_t sb = smem_u32(smem);
    const int tid = threadIdx.x;

    {
        const __half** s_ptr = (const __half**)smem;
        int* s_pred = (int*)(smem + 1536);
        if (tid < 64) {
            int p = m0 + tid;
            bool v = p < M;
            size_t ar = ((size_t)(e * PMAX64 + (v ? p : 0))) * HID;
            s_ptr[tid] = g_y1h + ar;
            s_pred[tid] = v ? 16 : 0;
        } else if (tid < 192) {
            int r = tid - 64;
            s_ptr[64 + r] = g_w2 + ((size_t)e * DIM + n0 + r) * HID;
        }
    }
    __syncthreads();

    float acc[2][4][4];
    gemm_mainloop(smem, sb, tid, acc);

    const int lane = tid & 31, wid = tid >> 5;
    const int wr = wid >> 2, wc = wid & 3;
    const int gid = lane >> 2, tig = lane & 3;
    const float* b2e = b2 + e * DIM + n0 + wc * 32;
#pragma unroll
    for (int mt = 0; mt < 2; mt++) {
        const int p0 = m0 + wr * 32 + mt * 16 + gid;
        const int p1 = p0 + 8;
        const bool v0 = p0 < M, v1 = p1 < M;
        int tok0 = 0, slot0 = 0, tok1 = 0, slot1 = 0;
        float w0 = 0.f, w1 = 0.f;
        if (v0) { tok0 = g_ptok[e * PMAX64 + p0]; slot0 = g_pslot[e * PMAX64 + p0]; w0 = g_pw[e * PMAX64 + p0]; }
        if (v1) { tok1 = g_ptok[e * PMAX64 + p1]; slot1 = g_pslot[e * PMAX64 + p1]; w1 = g_pw[e * PMAX64 + p1]; }
        float* d0 = g_pout + ((size_t)(tok0 * 4 + slot0)) * DIM + n0 + wc * 32;
        float* d1 = g_pout + ((size_t)(tok1 * 4 + slot1)) * DIM + n0 + wc * 32;
#pragma unroll
        for (int nt = 0; nt < 4; nt++) {
            const int co = nt * 8 + 2 * tig;
            const float* c = acc[mt][nt];
            if (v0) *(float2*)(d0 + co) = make_float2(w0 * (c[0] + b2e[co]), w0 * (c[1] + b2e[co + 1]));
            if (v1) *(float2*)(d1 + co) = make_float2(w1 * (c[2] + b2e[co]), w1 * (c[3] + b2e[co + 1]));
        }
    }
}

// ---------------- combine ----------------
__global__ void combine_kernel(float* __restrict__ out) {
    const int n = blockIdx.x, tid = threadIdx.x;
    const int ne = g_nent[n];
    const int d = tid * 4;
    float4 s = make_float4(0.f, 0.f, 0.f, 0.f);
    for (int sl = 0; sl < ne; sl++) {
        float4 v = *(const float4*)(g_pout + ((size_t)(n * 4 + sl)) * DIM + d);
        s.x += v.x; s.y += v.y; s.z += v.z; s.w += v.w;
    }
    *(float4*)(out + (size_t)n * DIM + d) = s;
}

// ---------------- launch ----------------
extern "C" void kernel_launch(void* const* d_in, const int* in_sizes, int n_in,
                              void* d_out, int out_size) {
    const float* x  = (const float*)d_in[0];
    const float* rw = (const float*)d_in[1];
    const float* rb = (const float*)d_in[2];
    const float* w1 = (const float*)d_in[3];
    const float* b1 = (const float*)d_in[4];
    const float* w2 = (const float*)d_in[5];
    const float* b2 = (const float*)d_in[6];
    float* out = (float*)d_out;

    cudaFuncSetAttribute(gemm1_tc, cudaFuncAttributeMaxDynamicSharedMemorySize, SMEM_GEMM);
    cudaFuncSetAttribute(gemm2_tc, cudaFuncAttributeMaxDynamicSharedMemorySize, SMEM_GEMM);

    dim3 gg(HID / 128, PMAX64 / 64, NEXP);   // (8, 130, 8); dead tiles exit at top
    dim3 tg(DIM / 32, HID / 32, NEXP * 2);   // both weights in one launch

    // order chosen so gemm1_tc is launch index 3 (the one ncu captures)
    router_split_kernel<<<NTOK / 8, 256>>>(x, rw, rb);        // 0
    dispatch_kernel<<<1, 1024>>>();                            // 1
    tsplit_kernel<<<tg, dim3(32, 8)>>>(w1, w2);                // 2
    gemm1_tc<<<gg, 256, SMEM_GEMM>>>(b1);                      // 3  <- profiled
    gemm2_tc<<<gg, 256, SMEM_GEMM>>>(b2);                      // 4
    combine_kernel<<<NTOK, 256>>>(out);                        // 5
}

// round 15
// speedup vs baseline: 1.0744x; 1.0744x over previous
#include <cuda_runtime.h>
#include <cuda_fp16.h>
#include <math.h>
#include <stdint.h>

#define NTOK 8192
#define DIM  1024
#define NEXP 8
#define HID  1024
#define PMAX 8320            // 65 * 128; per-expert lists padded to 128
#define CAPACITY 1280.0f

#define KC     64            // K elements per pipeline stage (fp16: 128B rows)
#define NCHUNK 16            // 1024 / 64
#define NSTAGE 3
#define SPLIT_B (128 * 128)        // 16384 B: one 128x64 fp16 tile
#define STAGE_B (2 * SPLIT_B)      // A, B = 32768
#define HDR     2048               // 256 src ptrs
#define SMEM_GEMM (HDR + NSTAGE * STAGE_B)   // 100352 -> 2 CTAs/SM

// ---------------- scratch globals ----------------
__device__ int   g_topi[NTOK * 2];
__device__ float g_topw[NTOK * 2];
__device__ int   g_nent[NTOK];
__device__ int   g_cnt[NEXP];              // padded counts (multiple of 128)
__device__ int   g_ptok[NEXP * PMAX];
__device__ int   g_pslot[NEXP * PMAX];
__device__ float g_pw[NEXP * PMAX];
__device__ __align__(256) __half g_xh[(size_t)(NTOK + 1) * DIM];   // +1 zeroed dummy row
__device__ __align__(256) __half g_w1[(size_t)NEXP * HID * DIM];   // [e][n][k] fp16
__device__ __align__(256) __half g_w2[(size_t)NEXP * DIM * HID];   // [e][n][k] fp16
__device__ __align__(256) __half g_y1h[(size_t)NEXP * PMAX * HID];
__device__ float g_pout[(size_t)(NTOK * 4 + 1) * DIM];             // +1 dummy sink row

// ---------------- small helpers ----------------
__device__ __forceinline__ uint32_t packh2(__half a, __half b) {
    __half2 t = __halves2half2(a, b);
    return *reinterpret_cast<uint32_t*>(&t);
}
__device__ __forceinline__ float gelu_f(float v) {
    return 0.5f * v * (1.0f + erff(v * 0.70710678118654752f));
}
__device__ __forceinline__ uint32_t smem_u32(const void* p) {
    uint32_t a;
    asm("{ .reg .u64 t; cvta.to.shared.u64 t, %1; cvt.u32.u64 %0, t; }" : "=r"(a) : "l"(p));
    return a;
}

#define LDSM_X4(r, addr) \
    asm volatile("ldmatrix.sync.aligned.m8n8.x4.shared.b16 {%0,%1,%2,%3}, [%4];" \
        : "=r"((r)[0]), "=r"((r)[1]), "=r"((r)[2]), "=r"((r)[3]) : "r"(addr))
#define MMA16816H(c, a, b) \
    asm volatile("mma.sync.aligned.m16n8k16.row.col.f32.f16.f16.f32 " \
        "{%0,%1,%2,%3}, {%4,%5,%6,%7}, {%8,%9}, {%0,%1,%2,%3};" \
        : "+f"((c)[0]), "+f"((c)[1]), "+f"((c)[2]), "+f"((c)[3]) \
        : "r"((a)[0]), "r"((a)[1]), "r"((a)[2]), "r"((a)[3]), "r"((b)[0]), "r"((b)[1]))

// swizzled byte offset within a 128-row x 128B tile
__device__ __forceinline__ uint32_t swz(uint32_t row, uint32_t seg) {
    return row * 128u + ((seg ^ (row & 7u)) * 16u);
}

// ---------------- fused router + x->fp16 ----------------
__global__ __launch_bounds__(256) void router_split_kernel(
        const float* __restrict__ x,
        const float* __restrict__ rw,
        const float* __restrict__ rb) {
    __shared__ float s_rw[DIM * 9];          // [k*9 + e]
    const int tid = threadIdx.x, lane = tid & 31, wid = tid >> 5;
    for (int i = tid; i < DIM * NEXP; i += 256) {
        int k = i >> 3, e = i & 7;
        s_rw[k * 9 + e] = rw[i];
    }
    __syncthreads();

    const int n = blockIdx.x * 8 + wid;
    const float* xr = x + (size_t)n * DIM;
    float acc[NEXP];
#pragma unroll
    for (int e = 0; e < NEXP; e++) acc[e] = 0.f;

#pragma unroll 4
    for (int i = 0; i < 16; i++) {
        const int k = i * 64 + lane * 2;
        float2 v = *(const float2*)(xr + k);
        *(uint32_t*)(g_xh + (size_t)n * DIM + k) =
            packh2(__float2half_rn(v.x), __float2half_rn(v.y));
        const float* r0 = s_rw + k * 9;
        const float* r1 = s_rw + (k + 1) * 9;
#pragma unroll
        for (int e = 0; e < NEXP; e++) acc[e] += v.x * r0[e] + v.y * r1[e];
    }
#pragma unroll
    for (int off = 16; off > 0; off >>= 1)
#pragma unroll
        for (int e = 0; e < NEXP; e++)
            acc[e] += __shfl_xor_sync(0xFFFFFFFFu, acc[e], off);

    if (lane == 0) {
        float l[NEXP];
#pragma unroll
        for (int e = 0; e < NEXP; e++) l[e] = acc[e] + rb[e];
        float m = l[0];
#pragma unroll
        for (int e = 1; e < NEXP; e++) m = fmaxf(m, l[e]);
        float p[NEXP], sum = 0.f;
#pragma unroll
        for (int e = 0; e < NEXP; e++) { p[e] = expf(l[e] - m); sum += p[e]; }
#pragma unroll
        for (int e = 0; e < NEXP; e++) p[e] /= sum;
        int i0 = 0;
        for (int e = 1; e < NEXP; e++) if (p[e] > p[i0]) i0 = e;
        int i1 = (i0 == 0) ? 1 : 0;
        for (int e = 0; e < NEXP; e++) if (e != i0 && p[e] > p[i1]) i1 = e;
        float s2 = p[i0] + p[i1];
        g_topi[n * 2 + 0] = i0;  g_topi[n * 2 + 1] = i1;
        g_topw[n * 2 + 0] = p[i0] / s2;  g_topw[n * 2 + 1] = p[i1] / s2;
    }
}

// ---------------- fused corr + dispatch build + pad (ONE block, 1024 threads) ----------------
__global__ __launch_bounds__(1024) void dispatch_kernel() {
    __shared__ float s_wred[32][16];
    __shared__ float s_corr[16];
    __shared__ int   s_cnt[NEXP];
    const int tid = threadIdx.x, lane = tid & 31, wid = tid >> 5;

    // zero the dummy x row (read by padded GEMM1 entries)
    for (int i = tid; i < DIM / 2; i += 1024)
        *(uint32_t*)(g_xh + (size_t)NTOK * DIM + i * 2) = 0;

    float a[16];
#pragma unroll
    for (int q = 0; q < 16; q++) a[q] = 0.f;
    for (int i = tid; i < NTOK; i += 1024) {
        int e0 = g_topi[i * 2 + 0], e1 = g_topi[i * 2 + 1];
        float w0 = g_topw[i * 2 + 0], w1 = g_topw[i * 2 + 1];
#pragma unroll
        for (int e = 0; e < NEXP; e++) {
            a[e * 2 + 0] += (e0 == e) ? w0 : 0.f;
            a[e * 2 + 1] += (e1 == e) ? w1 : 0.f;
        }
    }
#pragma unroll
    for (int off = 16; off > 0; off >>= 1)
#pragma unroll
        for (int q = 0; q < 16; q++)
            a[q] += __shfl_xor_sync(0xFFFFFFFFu, a[q], off);
    if (lane == 0)
#pragma unroll
        for (int q = 0; q < 16; q++) s_wred[wid][q] = a[q];
    if (tid < NEXP) s_cnt[tid] = 0;
    __syncthreads();
    if (tid < 16) {
        float s = 0.f;
        for (int w = 0; w < 32; w++) s += s_wred[w][tid];
        s_corr[tid] = s;
    }
    __syncthreads();

    for (int n = tid; n < NTOK; n += 1024) {
        int ee[4]; float ww[4]; int ne = 2;
        ee[0] = g_topi[n * 2 + 0]; ww[0] = g_topw[n * 2 + 0];
        ee[1] = g_topi[n * 2 + 1]; ww[1] = g_topw[n * 2 + 1];
        if (n < NEXP) {
#pragma unroll
            for (int j = 0; j < 2; j++) {
                float c = s_corr[n * 2 + j];
                int f = -1;
                for (int s = 0; s < ne; s++) if (ee[s] == j) f = s;
                if (f >= 0) ww[f] += c;
                else if (c != 0.0f) { ee[ne] = j; ww[ne] = c; ne++; }
            }
        }
        g_nent[n] = ne;
        for (int s = 0; s < ne; s++) {
            float w = fminf(ww[s], CAPACITY);
            int e = ee[s];
            int idx = atomicAdd(&s_cnt[e], 1);
            g_ptok[e * PMAX + idx] = n;
            g_pslot[e * PMAX + idx] = s;
            g_pw[e * PMAX + idx] = w;
        }
    }
    __syncthreads();

    // pad each expert list to a multiple of 128 with dummy entries
    // dummy: token NTOK (zeroed x row), slot 0, weight 0; gemm2 routes its
    // output to pout row NTOK*4 (sink, never read by combine)
    {
        const int e = tid >> 7, j = tid & 127;
        if (e < NEXP) {
            int start = s_cnt[e];
            int end = (start + 127) & ~127;
            int idx = start + j;
            if (idx < end) {
                g_ptok[e * PMAX + idx] = NTOK;
                g_pslot[e * PMAX + idx] = 0;
                g_pw[e * PMAX + idx] = 0.f;
            }
            if (j == 0) g_cnt[e] = end;
        }
    }
}

// ---------------- prep: transpose BOTH weights  w[e][k][n] -> [e][n][k] fp16 ----------------
__global__ void tsplit_kernel(const float* __restrict__ w1s, const float* __restrict__ w2s) {
    __shared__ float t[32][33];
    const int z = blockIdx.z;
    const int e = z & 7;
    const float* w = (z < 8) ? w1s : w2s;
    __half* oh = (z < 8) ? g_w1 : g_w2;
    int k0 = blockIdx.y * 32, n0 = blockIdx.x * 32;
    int tx = threadIdx.x, ty = threadIdx.y;
    const float* wp = w + (size_t)e * DIM * HID;
#pragma unroll
    for (int r = 0; r < 32; r += 8)
        t[ty + r][tx] = wp[(size_t)(k0 + ty + r) * HID + n0 + tx];
    __syncthreads();
#pragma unroll
    for (int r = 0; r < 32; r += 8) {
        float v = t[tx][ty + r];
        size_t o = ((size_t)e * HID + n0 + ty + r) * DIM + k0 + tx;
        oh[o] = __float2half_rn(v);
    }
}

// ---------------- GEMM mainloop (128x128 CTA tile, no predication) ----------------
__device__ __forceinline__ void load_stage(char* smem, uint32_t sb, int tid, int c) {
    const __half* const* s_ptr = (const __half* const*)smem;     // 256 entries
    const int kel = c * KC;
    const uint32_t sbase = sb + HDR + (uint32_t)((c % NSTAGE) * STAGE_B);
#pragma unroll
    for (int it = 0; it < 8; it++) {
        const int id = tid + it * 256;
        const int region = id >> 10, within = id & 1023;
        const int row = within >> 3, seg = within & 7;
        const char* src = (const char*)(s_ptr[region * 128 + row] + kel) + seg * 16;
        uint32_t dst = sbase + (uint32_t)(region * SPLIT_B) + swz(row, seg);
        asm volatile("cp.async.cg.shared.global [%0], [%1], 16, 16;"
                     :: "r"(dst), "l"(src) : "memory");
    }
    asm volatile("cp.async.commit_group;" ::: "memory");
}

__device__ __forceinline__ void compute_stage(uint32_t sb, int tid, int buf, float acc[4][4][4]) {
    const int lane = tid & 31, wid = tid >> 5;
    const int wr = wid >> 2, wc = wid & 3;
    const uint32_t base = sb + HDR + (uint32_t)(buf * STAGE_B);
    const uint32_t arow = wr * 64 + (lane & 15);
    const uint32_t asegbit = (lane >> 4) & 1;
    const uint32_t brow = wc * 32 + ((lane >> 4) & 1) * 8 + (lane & 7);
    const uint32_t bsegbit = (lane >> 3) & 1;
#pragma unroll
    for (int kst = 0; kst < 4; kst++) {
        const uint32_t aseg = kst * 2 + asegbit;
        const uint32_t bseg = kst * 2 + bsegbit;
        uint32_t ah[4][4], bb[2][4];
        // interleaved: first MMA's operands load first
        LDSM_X4(ah[0], base + swz(arow, aseg));
        LDSM_X4(bb[0], base + SPLIT_B + swz(brow, bseg));
        LDSM_X4(bb[1], base + SPLIT_B + swz(brow + 16, bseg));
        LDSM_X4(ah[1], base + swz(arow + 16, aseg));
        LDSM_X4(ah[2], base + swz(arow + 32, aseg));
        LDSM_X4(ah[3], base + swz(arow + 48, aseg));
#pragma unroll
        for (int mt = 0; mt < 4; mt++)
#pragma unroll
            for (int nt = 0; nt < 4; nt++)
                MMA16816H(acc[mt][nt], ah[mt], &bb[nt >> 1][(nt & 1) * 2]);
    }
}

__device__ __forceinline__ void gemm_mainloop(char* smem, uint32_t sb, int tid, float acc[4][4][4]) {
#pragma unroll
    for (int mt = 0; mt < 4; mt++)
#pragma unroll
        for (int nt = 0; nt < 4; nt++)
#pragma unroll
            for (int i = 0; i < 4; i++) acc[mt][nt][i] = 0.f;
    load_stage(smem, sb, tid, 0);
    load_stage(smem, sb, tid, 1);
#pragma unroll 1
    for (int c = 0; c < NCHUNK; c++) {
        if (c == NCHUNK - 1) asm volatile("cp.async.wait_group 0;" ::: "memory");
        else                 asm volatile("cp.async.wait_group 1;" ::: "memory");
        __syncthreads();   // c's data visible; buffer (c+2)%3 free (compute c-1 done)
        if (c + 2 < NCHUNK) load_stage(smem, sb, tid, c + 2);
        compute_stage(sb, tid, c % NSTAGE, acc);
    }
}

// ---------------- GEMM1: y1 = gelu(w * (x @ W1) + b1) -> fp16 ----------------
__global__ __launch_bounds__(256, 2) void gemm1_tc(const float* __restrict__ b1) {
    const int e = blockIdx.z;
    const int M = g_cnt[e];                   // multiple of 128
    const int m0 = blockIdx.y * 128;
    if (m0 >= M) return;
    const int n0 = blockIdx.x * 128;
    extern __shared__ char smem[];
    const uint32_t sb = smem_u32(smem);
    const int tid = threadIdx.x;

    {
        const __half** s_ptr = (const __half**)smem;
        if (tid < 128) {
            int tok = g_ptok[e * PMAX + m0 + tid];
            s_ptr[tid] = g_xh + (size_t)tok * DIM;
            s_ptr[128 + tid] = g_w1 + ((size_t)e * HID + n0 + tid) * DIM;
        }
    }
    __syncthreads();

    float acc[4][4][4];
    gemm_mainloop(smem, sb, tid, acc);

    const int lane = tid & 31, wid = tid >> 5;
    const int wr = wid >> 2, wc = wid & 3;
    const int gid = lane >> 2, tig = lane & 3;
    const float* b1e = b1 + e * HID + n0 + wc * 32;
#pragma unroll
    for (int mt = 0; mt < 4; mt++) {
        const int p0 = m0 + wr * 64 + mt * 16 + gid;
        const int p1 = p0 + 8;
        const float w0 = g_pw[e * PMAX + p0];
        const float w1 = g_pw[e * PMAX + p1];
        __half* oh0 = g_y1h + ((size_t)(e * PMAX + p0)) * HID + n0 + wc * 32;
        __half* oh1 = g_y1h + ((size_t)(e * PMAX + p1)) * HID + n0 + wc * 32;
#pragma unroll
        for (int nt = 0; nt < 4; nt++) {
            const int co = nt * 8 + 2 * tig;
            const float* c = acc[mt][nt];
            float t0 = gelu_f(w0 * c[0] + b1e[co]);
            float t1 = gelu_f(w0 * c[1] + b1e[co + 1]);
            *(uint32_t*)(oh0 + co) = packh2(__float2half_rn(t0), __float2half_rn(t1));
            float t2 = gelu_f(w1 * c[2] + b1e[co]);
            float t3 = gelu_f(w1 * c[3] + b1e[co + 1]);
            *(uint32_t*)(oh1 + co) = packh2(__float2half_rn(t2), __float2half_rn(t3));
        }
    }
}

// ---------------- GEMM2: pout = w * (y1 @ W2 + b2) ----------------
__global__ __launch_bounds__(256, 2) void gemm2_tc(const float* __restrict__ b2) {
    const int e = blockIdx.z;
    const int M = g_cnt[e];
    const int m0 = blockIdx.y * 128;
    if (m0 >= M) return;
    const int n0 = blockIdx.x * 128;
    extern __shared__ char smem[];
    const uint32_t sb = smem_u32(smem);
    const int tid = threadIdx.x;

    {
        const __half** s_ptr = (const __half**)smem;
        if (tid < 128) {
            s_ptr[tid] = g_y1h + ((size_t)(e * PMAX + m0 + tid)) * HID;
            s_ptr[128 + tid] = g_w2 + ((size_t)e * DIM + n0 + tid) * HID;
        }
    }
    __syncthreads();

    float acc[4][4][4];
    gemm_mainloop(smem, sb, tid, acc);

    const int lane = tid & 31, wid = tid >> 5;
    const int wr = wid >> 2, wc = wid & 3;
    const int gid = lane >> 2, tig = lane & 3;
    const float* b2e = b2 + e * DIM + n0 + wc * 32;
#pragma unroll
    for (int mt = 0; mt < 4; mt++) {
        const int p0 = m0 + wr * 64 + mt * 16 + gid;
        const int p1 = p0 + 8;
        const int tok0 = g_ptok[e * PMAX + p0];
        const int tok1 = g_ptok[e * PMAX + p1];
        const int slot0 = g_pslot[e * PMAX + p0];
        const int slot1 = g_pslot[e * PMAX + p1];
        const float w0 = g_pw[e * PMAX + p0];
        const float w1 = g_pw[e * PMAX + p1];
        float* d0 = g_pout + ((size_t)(tok0 * 4 + slot0)) * DIM + n0 + wc * 32;
        float* d1 = g_pout + ((size_t)(tok1 * 4 + slot1)) * DIM + n0 + wc * 32;
#pragma unroll
        for (int nt = 0; nt < 4; nt++) {
            const int co = nt * 8 + 2 * tig;
            const float* c = acc[mt][nt];
            *(float2*)(d0 + co) = make_float2(w0 * (c[0] + b2e[co]), w0 * (c[1] + b2e[co + 1]));
            *(float2*)(d1 + co) = make_float2(w1 * (c[2] + b2e[co]), w1 * (c[3] + b2e[co + 1]));
        }
    }
}

// ---------------- combine ----------------
__global__ void combine_kernel(float* __restrict__ out) {
    const int n = blockIdx.x, tid = threadIdx.x;
    const int ne = g_nent[n];
    const int d = tid * 4;
    float4 s = make_float4(0.f, 0.f, 0.f, 0.f);
    for (int sl = 0; sl < ne; sl++) {
        float4 v = *(const float4*)(g_pout + ((size_t)(n * 4 + sl)) * DIM + d);
        s.x += v.x; s.y += v.y; s.z += v.z; s.w += v.w;
    }
    *(float4*)(out + (size_t)n * DIM + d) = s;
}

// ---------------- launch ----------------
extern "C" void kernel_launch(void* const* d_in, const int* in_sizes, int n_in,
                              void* d_out, int out_size) {
    const float* x  = (const float*)d_in[0];
    const float* rw = (const float*)d_in[1];
    const float* rb = (const float*)d_in[2];
    const float* w1 = (const float*)d_in[3];
    const float* b1 = (const float*)d_in[4];
    const float* w2 = (const float*)d_in[5];
    const float* b2 = (const float*)d_in[6];
    float* out = (float*)d_out;

    cudaFuncSetAttribute(gemm1_tc, cudaFuncAttributeMaxDynamicSharedMemorySize, SMEM_GEMM);
    cudaFuncSetAttribute(gemm2_tc, cudaFuncAttributeMaxDynamicSharedMemorySize, SMEM_GEMM);

    dim3 gg(HID / 128, PMAX / 128, NEXP);    // (8, 65, 8); dead tiles exit at top
    dim3 tg(DIM / 32, HID / 32, NEXP * 2);   // both weights in one launch

    // order chosen so gemm1_tc is launch index 3 (the one ncu captures)
    router_split_kernel<<<NTOK / 8, 256>>>(x, rw, rb);        // 0
    dispatch_kernel<<<1, 1024>>>();                            // 1
    tsplit_kernel<<<tg, dim3(32, 8)>>>(w1, w2);                // 2
    gemm1_tc<<<gg, 256, SMEM_GEMM>>>(b1);                      // 3  <- profiled
    gemm2_tc<<<gg, 256, SMEM_GEMM>>>(b2);                      // 4
    combine_kernel<<<NTOK, 256>>>(out);                        // 5
}

// round 16
// speedup vs baseline: 1.0811x; 1.0062x over previous
#include <cuda_runtime.h>
#include <cuda_fp16.h>
#include <math.h>
#include <stdint.h>

#define NTOK 8192
#define DIM  1024
#define NEXP 8
#define HID  1024
#define PMAX 8320            // 65 * 128; per-expert lists padded to 128
#define CAPACITY 1280.0f

#define KC     64            // K elements per pipeline stage (fp16: 128B rows)
#define NCHUNK 16            // 1024 / 64
#define NSTAGE 3
#define SPLIT_B (128 * 128)        // 16384 B: one 128x64 fp16 tile
#define STAGE_B (2 * SPLIT_B)      // A, B = 32768
#define HDR     2048               // 256 src ptrs
#define SMEM_GEMM (HDR + NSTAGE * STAGE_B)   // 100352 -> 2 CTAs/SM

// ---------------- scratch globals ----------------
__device__ int   g_topi[NTOK * 2];
__device__ float g_topw[NTOK * 2];
__device__ int   g_nent[NTOK];
__device__ int   g_cnt[NEXP];              // padded counts (multiple of 128)
__device__ int   g_ptok[NEXP * PMAX];
__device__ int   g_pslot[NEXP * PMAX];
__device__ float g_pw[NEXP * PMAX];
__device__ __align__(256) __half g_xh[(size_t)(NTOK + 1) * DIM];   // +1 zeroed dummy row
__device__ __align__(256) __half g_w1[(size_t)NEXP * HID * DIM];   // [e][n][k] fp16
__device__ __align__(256) __half g_w2[(size_t)NEXP * DIM * HID];   // [e][n][k] fp16
__device__ __align__(256) __half g_y1h[(size_t)NEXP * PMAX * HID];
__device__ float g_pout[(size_t)(NTOK * 4 + 1) * DIM];             // +1 dummy sink row

// ---------------- small helpers ----------------
__device__ __forceinline__ uint32_t packh2(__half a, __half b) {
    __half2 t = __halves2half2(a, b);
    return *reinterpret_cast<uint32_t*>(&t);
}
__device__ __forceinline__ float gelu_f(float v) {
    return 0.5f * v * (1.0f + erff(v * 0.70710678118654752f));
}
__device__ __forceinline__ uint32_t smem_u32(const void* p) {
    uint32_t a;
    asm("{ .reg .u64 t; cvta.to.shared.u64 t, %1; cvt.u32.u64 %0, t; }" : "=r"(a) : "l"(p));
    return a;
}

#define LDSM_X4(r, addr) \
    asm volatile("ldmatrix.sync.aligned.m8n8.x4.shared.b16 {%0,%1,%2,%3}, [%4];" \
        : "=r"((r)[0]), "=r"((r)[1]), "=r"((r)[2]), "=r"((r)[3]) : "r"(addr))
#define MMA16816H(c, a, b) \
    asm volatile("mma.sync.aligned.m16n8k16.row.col.f32.f16.f16.f32 " \
        "{%0,%1,%2,%3}, {%4,%5,%6,%7}, {%8,%9}, {%0,%1,%2,%3};" \
        : "+f"((c)[0]), "+f"((c)[1]), "+f"((c)[2]), "+f"((c)[3]) \
        : "r"((a)[0]), "r"((a)[1]), "r"((a)[2]), "r"((a)[3]), "r"((b)[0]), "r"((b)[1]))

// swizzled byte offset within a 128-row x 128B tile
__device__ __forceinline__ uint32_t swz(uint32_t row, uint32_t seg) {
    return row * 128u + ((seg ^ (row & 7u)) * 16u);
}

// ---------------- fused router + x->fp16 ----------------
__global__ __launch_bounds__(256) void router_split_kernel(
        const float* __restrict__ x,
        const float* __restrict__ rw,
        const float* __restrict__ rb) {
    __shared__ float s_rw[DIM * 9];          // [k*9 + e]
    const int tid = threadIdx.x, lane = tid & 31, wid = tid >> 5;
    for (int i = tid; i < DIM * NEXP; i += 256) {
        int k = i >> 3, e = i & 7;
        s_rw[k * 9 + e] = rw[i];
    }
    __syncthreads();

    const int n = blockIdx.x * 8 + wid;
    const float* xr = x + (size_t)n * DIM;
    float acc[NEXP];
#pragma unroll
    for (int e = 0; e < NEXP; e++) acc[e] = 0.f;

#pragma unroll 4
    for (int i = 0; i < 16; i++) {
        const int k = i * 64 + lane * 2;
        float2 v = *(const float2*)(xr + k);
        *(uint32_t*)(g_xh + (size_t)n * DIM + k) =
            packh2(__float2half_rn(v.x), __float2half_rn(v.y));
        const float* r0 = s_rw + k * 9;
        const float* r1 = s_rw + (k + 1) * 9;
#pragma unroll
        for (int e = 0; e < NEXP; e++) acc[e] += v.x * r0[e] + v.y * r1[e];
    }
#pragma unroll
    for (int off = 16; off > 0; off >>= 1)
#pragma unroll
        for (int e = 0; e < NEXP; e++)
            acc[e] += __shfl_xor_sync(0xFFFFFFFFu, acc[e], off);

    if (lane == 0) {
        float l[NEXP];
#pragma unroll
        for (int e = 0; e < NEXP; e++) l[e] = acc[e] + rb[e];
        float m = l[0];
#pragma unroll
        for (int e = 1; e < NEXP; e++) m = fmaxf(m, l[e]);
        float p[NEXP], sum = 0.f;
#pragma unroll
        for (int e = 0; e < NEXP; e++) { p[e] = expf(l[e] - m); sum += p[e]; }
#pragma unroll
        for (int e = 0; e < NEXP; e++) p[e] /= sum;
        int i0 = 0;
        for (int e = 1; e < NEXP; e++) if (p[e] > p[i0]) i0 = e;
        int i1 = (i0 == 0) ? 1 : 0;
        for (int e = 0; e < NEXP; e++) if (e != i0 && p[e] > p[i1]) i1 = e;
        float s2 = p[i0] + p[i1];
        g_topi[n * 2 + 0] = i0;  g_topi[n * 2 + 1] = i1;
        g_topw[n * 2 + 0] = p[i0] / s2;  g_topw[n * 2 + 1] = p[i1] / s2;
    }
}

// ---------------- fused corr + dispatch build + pad (ONE block, 1024 threads) ----------------
__global__ __launch_bounds__(1024) void dispatch_kernel() {
    __shared__ float s_wred[32][16];
    __shared__ float s_corr[16];
    __shared__ int   s_cnt[NEXP];
    const int tid = threadIdx.x, lane = tid & 31, wid = tid >> 5;

    // zero the dummy x row (read by padded GEMM1 entries)
    for (int i = tid; i < DIM / 2; i += 1024)
        *(uint32_t*)(g_xh + (size_t)NTOK * DIM + i * 2) = 0;

    float a[16];
#pragma unroll
    for (int q = 0; q < 16; q++) a[q] = 0.f;
    for (int i = tid; i < NTOK; i += 1024) {
        int e0 = g_topi[i * 2 + 0], e1 = g_topi[i * 2 + 1];
        float w0 = g_topw[i * 2 + 0], w1 = g_topw[i * 2 + 1];
#pragma unroll
        for (int e = 0; e < NEXP; e++) {
            a[e * 2 + 0] += (e0 == e) ? w0 : 0.f;
            a[e * 2 + 1] += (e1 == e) ? w1 : 0.f;
        }
    }
#pragma unroll
    for (int off = 16; off > 0; off >>= 1)
#pragma unroll
        for (int q = 0; q < 16; q++)
            a[q] += __shfl_xor_sync(0xFFFFFFFFu, a[q], off);
    if (lane == 0)
#pragma unroll
        for (int q = 0; q < 16; q++) s_wred[wid][q] = a[q];
    if (tid < NEXP) s_cnt[tid] = 0;
    __syncthreads();
    if (tid < 16) {
        float s = 0.f;
        for (int w = 0; w < 32; w++) s += s_wred[w][tid];
        s_corr[tid] = s;
    }
    __syncthreads();

    for (int n = tid; n < NTOK; n += 1024) {
        int ee[4]; float ww[4]; int ne = 2;
        ee[0] = g_topi[n * 2 + 0]; ww[0] = g_topw[n * 2 + 0];
        ee[1] = g_topi[n * 2 + 1]; ww[1] = g_topw[n * 2 + 1];
        if (n < NEXP) {
#pragma unroll
            for (int j = 0; j < 2; j++) {
                float c = s_corr[n * 2 + j];
                int f = -1;
                for (int s = 0; s < ne; s++) if (ee[s] == j) f = s;
                if (f >= 0) ww[f] += c;
                else if (c != 0.0f) { ee[ne] = j; ww[ne] = c; ne++; }
            }
        }
        g_nent[n] = ne;
        for (int s = 0; s < ne; s++) {
            float w = fminf(ww[s], CAPACITY);
            int e = ee[s];
            int idx = atomicAdd(&s_cnt[e], 1);
            g_ptok[e * PMAX + idx] = n;
            g_pslot[e * PMAX + idx] = s;
            g_pw[e * PMAX + idx] = w;
        }
    }
    __syncthreads();

    // pad each expert list to a multiple of 128 with dummy entries
    {
        const int e = tid >> 7, j = tid & 127;
        if (e < NEXP) {
            int start = s_cnt[e];
            int end = (start + 127) & ~127;
            int idx = start + j;
            if (idx < end) {
                g_ptok[e * PMAX + idx] = NTOK;
                g_pslot[e * PMAX + idx] = 0;
                g_pw[e * PMAX + idx] = 0.f;
            }
            if (j == 0) g_cnt[e] = end;
        }
    }
}

// ---------------- prep: transpose BOTH weights  w[e][k][n] -> [e][n][k] fp16 ----------------
__global__ void tsplit_kernel(const float* __restrict__ w1s, const float* __restrict__ w2s) {
    __shared__ float t[32][33];
    const int z = blockIdx.z;
    const int e = z & 7;
    const float* w = (z < 8) ? w1s : w2s;
    __half* oh = (z < 8) ? g_w1 : g_w2;
    int k0 = blockIdx.y * 32, n0 = blockIdx.x * 32;
    int tx = threadIdx.x, ty = threadIdx.y;
    const float* wp = w + (size_t)e * DIM * HID;
#pragma unroll
    for (int r = 0; r < 32; r += 8)
        t[ty + r][tx] = wp[(size_t)(k0 + ty + r) * HID + n0 + tx];
    __syncthreads();
#pragma unroll
    for (int r = 0; r < 32; r += 8) {
        float v = t[tx][ty + r];
        size_t o = ((size_t)e * HID + n0 + ty + r) * DIM + k0 + tx;
        oh[o] = __float2half_rn(v);
    }
}

// ---------------- GEMM mainloop (128x128 CTA tile, kst-pipelined) ----------------
__device__ __forceinline__ void load_stage(char* smem, uint32_t sb, int tid, int c) {
    const __half* const* s_ptr = (const __half* const*)smem;     // 256 entries
    const int kel = c * KC;
    const uint32_t sbase = sb + HDR + (uint32_t)((c % NSTAGE) * STAGE_B);
#pragma unroll
    for (int it = 0; it < 8; it++) {
        const int id = tid + it * 256;
        const int region = id >> 10, within = id & 1023;
        const int row = within >> 3, seg = within & 7;
        const char* src = (const char*)(s_ptr[region * 128 + row] + kel) + seg * 16;
        uint32_t dst = sbase + (uint32_t)(region * SPLIT_B) + swz(row, seg);
        asm volatile("cp.async.cg.shared.global [%0], [%1], 16, 16;"
                     :: "r"(dst), "l"(src) : "memory");
    }
    asm volatile("cp.async.commit_group;" ::: "memory");
}

__device__ __forceinline__ void lds_frag_a(uint32_t base, uint32_t arow, uint32_t aseg,
                                           uint32_t ah[4][4]) {
    LDSM_X4(ah[0], base + swz(arow, aseg));
    LDSM_X4(ah[1], base + swz(arow + 16, aseg));
    LDSM_X4(ah[2], base + swz(arow + 32, aseg));
    LDSM_X4(ah[3], base + swz(arow + 48, aseg));
}
__device__ __forceinline__ void lds_frag_b(uint32_t base, uint32_t brow, uint32_t bseg,
                                           uint32_t bb[2][4]) {
    LDSM_X4(bb[0], base + SPLIT_B + swz(brow, bseg));
    LDSM_X4(bb[1], base + SPLIT_B + swz(brow + 16, bseg));
}

__device__ __forceinline__ void compute_stage(uint32_t sb, int tid, int buf, float acc[4][4][4]) {
    const int lane = tid & 31, wid = tid >> 5;
    const int wr = wid >> 2, wc = wid & 3;
    const uint32_t base = sb + HDR + (uint32_t)(buf * STAGE_B);
    const uint32_t arow = wr * 64 + (lane & 15);
    const uint32_t asegbit = (lane >> 4) & 1;
    const uint32_t brow = wc * 32 + ((lane >> 4) & 1) * 8 + (lane & 7);
    const uint32_t bsegbit = (lane >> 3) & 1;

    uint32_t ah[2][4][4], bb[2][2][4];
    // preload kst 0
    lds_frag_a(base, arow, asegbit, ah[0]);
    lds_frag_b(base, brow, bsegbit, bb[0]);
#pragma unroll
    for (int kst = 0; kst < 4; kst++) {
        const int cur = kst & 1, nxt = cur ^ 1;
        if (kst < 3) {      // prefetch kst+1 fragments during this kst's MMAs
            lds_frag_a(base, arow, (kst + 1) * 2 + asegbit, ah[nxt]);
            lds_frag_b(base, brow, (kst + 1) * 2 + bsegbit, bb[nxt]);
        }
#pragma unroll
        for (int mt = 0; mt < 4; mt++)
#pragma unroll
            for (int nt = 0; nt < 4; nt++)
                MMA16816H(acc[mt][nt], ah[cur][mt], &bb[cur][nt >> 1][(nt & 1) * 2]);
    }
}

__device__ __forceinline__ void gemm_mainloop(char* smem, uint32_t sb, int tid, float acc[4][4][4]) {
#pragma unroll
    for (int mt = 0; mt < 4; mt++)
#pragma unroll
        for (int nt = 0; nt < 4; nt++)
#pragma unroll
            for (int i = 0; i < 4; i++) acc[mt][nt][i] = 0.f;
    load_stage(smem, sb, tid, 0);
    load_stage(smem, sb, tid, 1);
#pragma unroll 1
    for (int c = 0; c < NCHUNK; c++) {
        if (c == NCHUNK - 1) asm volatile("cp.async.wait_group 0;" ::: "memory");
        else                 asm volatile("cp.async.wait_group 1;" ::: "memory");
        __syncthreads();   // c's data visible; buffer (c+2)%3 free (compute c-1 done)
        if (c + 2 < NCHUNK) load_stage(smem, sb, tid, c + 2);
        compute_stage(sb, tid, c % NSTAGE, acc);
    }
}

// ---------------- GEMM1: y1 = gelu(w * (x @ W1) + b1) -> fp16 ----------------
__global__ __launch_bounds__(256, 2) void gemm1_tc(const float* __restrict__ b1) {
    const int e = blockIdx.z;
    const int M = g_cnt[e];                   // multiple of 128
    const int m0 = blockIdx.y * 128;
    if (m0 >= M) return;
    const int n0 = blockIdx.x * 128;
    extern __shared__ char smem[];
    const uint32_t sb = smem_u32(smem);
    const int tid = threadIdx.x;

    {
        const __half** s_ptr = (const __half**)smem;
        if (tid < 128) {
            int tok = g_ptok[e * PMAX + m0 + tid];
            s_ptr[tid] = g_xh + (size_t)tok * DIM;
            s_ptr[128 + tid] = g_w1 + ((size_t)e * HID + n0 + tid) * DIM;
        }
    }
    __syncthreads();

    float acc[4][4][4];
    gemm_mainloop(smem, sb, tid, acc);

    const int lane = tid & 31, wid = tid >> 5;
    const int wr = wid >> 2, wc = wid & 3;
    const int gid = lane >> 2, tig = lane & 3;
    const float* b1e = b1 + e * HID + n0 + wc * 32;
#pragma unroll
    for (int mt = 0; mt < 4; mt++) {
        const int p0 = m0 + wr * 64 + mt * 16 + gid;
        const int p1 = p0 + 8;
        const float w0 = g_pw[e * PMAX + p0];
        const float w1 = g_pw[e * PMAX + p1];
        __half* oh0 = g_y1h + ((size_t)(e * PMAX + p0)) * HID + n0 + wc * 32;
        __half* oh1 = g_y1h + ((size_t)(e * PMAX + p1)) * HID + n0 + wc * 32;
#pragma unroll
        for (int nt = 0; nt < 4; nt++) {
            const int co = nt * 8 + 2 * tig;
            const float* c = acc[mt][nt];
            float t0 = gelu_f(w0 * c[0] + b1e[co]);
            float t1 = gelu_f(w0 * c[1] + b1e[co + 1]);
            *(uint32_t*)(oh0 + co) = packh2(__float2half_rn(t0), __float2half_rn(t1));
            float t2 = gelu_f(w1 * c[2] + b1e[co]);
            float t3 = gelu_f(w1 * c[3] + b1e[co + 1]);
            *(uint32_t*)(oh1 + co) = packh2(__float2half_rn(t2), __float2half_rn(t3));
        }
    }
}

// ---------------- GEMM2: pout = w * (y1 @ W2 + b2) ----------------
__global__ __launch_bounds__(256, 2) void gemm2_tc(const float* __restrict__ b2) {
    const int e = blockIdx.z;
    const int M = g_cnt[e];
    const int m0 = blockIdx.y * 128;
    if (m0 >= M) return;
    const int n0 = blockIdx.x * 128;
    extern __shared__ char smem[];
    const uint32_t sb = smem_u32(smem);
    const int tid = threadIdx.x;

    {
        const __half** s_ptr = (const __half**)smem;
        if (tid < 128) {
            s_ptr[tid] = g_y1h + ((size_t)(e * PMAX + m0 + tid)) * HID;
            s_ptr[128 + tid] = g_w2 + ((size_t)e * DIM + n0 + tid) * HID;
        }
    }
    __syncthreads();

    float acc[4][4][4];
    gemm_mainloop(smem, sb, tid, acc);

    const int lane = tid & 31, wid = tid >> 5;
    const int wr = wid >> 2, wc = wid & 3;
    const int gid = lane >> 2, tig = lane & 3;
    const float* b2e = b2 + e * DIM + n0 + wc * 32;
#pragma unroll
    for (int mt = 0; mt < 4; mt++) {
        const int p0 = m0 + wr * 64 + mt * 16 + gid;
        const int p1 = p0 + 8;
        const int tok0 = g_ptok[e * PMAX + p0];
        const int tok1 = g_ptok[e * PMAX + p1];
        const int slot0 = g_pslot[e * PMAX + p0];
        const int slot1 = g_pslot[e * PMAX + p1];
        const float w0 = g_pw[e * PMAX + p0];
        const float w1 = g_pw[e * PMAX + p1];
        float* d0 = g_pout + ((size_t)(tok0 * 4 + slot0)) * DIM + n0 + wc * 32;
        float* d1 = g_pout + ((size_t)(tok1 * 4 + slot1)) * DIM + n0 + wc * 32;
#pragma unroll
        for (int nt = 0; nt < 4; nt++) {
            const int co = nt * 8 + 2 * tig;
            const float* c = acc[mt][nt];
            *(float2*)(d0 + co) = make_float2(w0 * (c[0] + b2e[co]), w0 * (c[1] + b2e[co + 1]));
            *(float2*)(d1 + co) = make_float2(w1 * (c[2] + b2e[co]), w1 * (c[3] + b2e[co + 1]));
        }
    }
}

// ---------------- combine ----------------
__global__ void combine_kernel(float* __restrict__ out) {
    const int n = blockIdx.x, tid = threadIdx.x;
    const int ne = g_nent[n];
    const int d = tid * 4;
    float4 s = make_float4(0.f, 0.f, 0.f, 0.f);
    for (int sl = 0; sl < ne; sl++) {
        float4 v = *(const float4*)(g_pout + ((size_t)(n * 4 + sl)) * DIM + d);
        s.x += v.x; s.y += v.y; s.z += v.z; s.w += v.w;
    }
    *(float4*)(out + (size_t)n * DIM + d) = s;
}

// ---------------- launch ----------------
extern "C" void kernel_launch(void* const* d_in, const int* in_sizes, int n_in,
                              void* d_out, int out_size) {
    const float* x  = (const float*)d_in[0];
    const float* rw = (const float*)d_in[1];
    const float* rb = (const float*)d_in[2];
    const float* w1 = (const float*)d_in[3];
    const float* b1 = (const float*)d_in[4];
    const float* w2 = (const float*)d_in[5];
    const float* b2 = (const float*)d_in[6];
    float* out = (float*)d_out;

    cudaFuncSetAttribute(gemm1_tc, cudaFuncAttributeMaxDynamicSharedMemorySize, SMEM_GEMM);
    cudaFuncSetAttribute(gemm2_tc, cudaFuncAttributeMaxDynamicSharedMemorySize, SMEM_GEMM);

    dim3 gg(HID / 128, PMAX / 128, NEXP);    // (8, 65, 8); dead tiles exit at top
    dim3 tg(DIM / 32, HID / 32, NEXP * 2);   // both weights in one launch

    // order chosen so gemm1_tc is launch index 3 (the one ncu captures)
    router_split_kernel<<<NTOK / 8, 256>>>(x, rw, rb);        // 0
    dispatch_kernel<<<1, 1024>>>();                            // 1
    tsplit_kernel<<<tg, dim3(32, 8)>>>(w1, w2);                // 2
    gemm1_tc<<<gg, 256, SMEM_GEMM>>>(b1);                      // 3  <- profiled
    gemm2_tc<<<gg, 256, SMEM_GEMM>>>(b2);                      // 4
    combine_kernel<<<NTOK, 256>>>(out);                        // 5
}